// round 1
// baseline (speedup 1.0000x reference)
#include <cuda_runtime.h>

#define T_ 8
#define B_ 4
#define C_ 128
#define HW_ 9216      // 96*96
#define HW4_ 2304     // HW_/4
#define NMAP 36       // T*B + B maps to resize
#define NTB 32        // T*B

// scratch (static __device__ — no allocation)
__device__ float g_tv[B_ * HW_];
__device__ float g_rv[NTB * HW_];
__device__ float g_cm[NTB * HW_];
__device__ float g_pgs[NTB * 9];
__device__ float g_pvs[NTB * 9];
__device__ float g_gs[NTB];

// ---------------------------------------------------------------------------
// 1) bilinear (antialiased, jax-style) 384->96 resize + threshold > 0.5
//    weights per axis: {1,3,5,7,7,5,3,1}/32, taps at 4o-2..4o+5, edge-renorm.
// ---------------------------------------------------------------------------
__global__ void resize_kernel(const float* __restrict__ tvmap,
                              const float* __restrict__ rvmaps) {
    int idx = blockIdx.x * blockDim.x + threadIdx.x;
    if (idx >= NMAP * HW_) return;
    int m = idx / HW_;
    int p = idx - m * HW_;
    int oy = p / 96, ox = p - oy * 96;

    const float* src = (m < B_) ? (tvmap + (size_t)m * 147456)
                                : (rvmaps + (size_t)(m - B_) * 147456);

    const float wtab[8] = {1.f, 3.f, 5.f, 7.f, 7.f, 5.f, 3.f, 1.f};
    int iy0 = 4 * oy - 2, ix0 = 4 * ox - 2;

    float wx[8];
    float wxs = 0.f;
#pragma unroll
    for (int k = 0; k < 8; k++) {
        int ix = ix0 + k;
        wx[k] = (ix >= 0 && ix < 384) ? wtab[k] : 0.f;
        wxs += wx[k];
    }

    float acc = 0.f, wys = 0.f;
#pragma unroll
    for (int ky = 0; ky < 8; ky++) {
        int iy = iy0 + ky;
        if (iy < 0 || iy >= 384) continue;
        wys += wtab[ky];
        const float* row = src + iy * 384;
        float ra = 0.f;
#pragma unroll
        for (int kx = 0; kx < 8; kx++) {
            if (wx[kx] != 0.f) ra += wx[kx] * row[ix0 + kx];
        }
        acc += wtab[ky] * ra;
    }
    float val = acc / (wys * wxs);
    float bin = (val > 0.5f) ? 1.f : 0.f;
    if (m < B_) g_tv[m * HW_ + p] = bin;
    else        g_rv[(m - B_) * HW_ + p] = bin;
}

// ---------------------------------------------------------------------------
// 2) masked correlation partials: for each (t,b) sum over pixels of
//    vmap * dot_c(t_feat, r_feat).  grid = (9 pixel tiles, 32 tb)
// ---------------------------------------------------------------------------
__global__ void __launch_bounds__(256) pass1_kernel(const float* __restrict__ values) {
    int tb = blockIdx.y;
    int b = tb & 3;
    int i4 = blockIdx.x * 256 + threadIdx.x;   // 0..2303

    const float4* tf = (const float4*)values + (size_t)b * C_ * HW4_;
    const float4* rf = (const float4*)values + (size_t)(B_ + tb) * C_ * HW4_;

    float4 acc = make_float4(0.f, 0.f, 0.f, 0.f);
#pragma unroll 4
    for (int c = 0; c < C_; c++) {
        float4 a = __ldg(tf + c * HW4_ + i4);
        float4 r = __ldg(rf + c * HW4_ + i4);
        acc.x += a.x * r.x; acc.y += a.y * r.y;
        acc.z += a.z * r.z; acc.w += a.w * r.w;
    }

    float4 tv = ((const float4*)g_tv)[b * HW4_ + i4];
    float4 rv = ((const float4*)g_rv)[tb * HW4_ + i4];
    float m0 = tv.x * rv.x, m1 = tv.y * rv.y, m2 = tv.z * rv.z, m3 = tv.w * rv.w;
    float lg = acc.x * m0 + acc.y * m1 + acc.z * m2 + acc.w * m3;
    float lv = m0 + m1 + m2 + m3;

#pragma unroll
    for (int o = 16; o > 0; o >>= 1) {
        lg += __shfl_down_sync(0xffffffffu, lg, o);
        lv += __shfl_down_sync(0xffffffffu, lv, o);
    }
    __shared__ float sg[8], sv[8];
    int lane = threadIdx.x & 31, w = threadIdx.x >> 5;
    if (lane == 0) { sg[w] = lg; sv[w] = lv; }
    __syncthreads();
    if (threadIdx.x == 0) {
        float a = 0.f, v = 0.f;
#pragma unroll
        for (int i = 0; i < 8; i++) { a += sg[i]; v += sv[i]; }
        g_pgs[tb * 9 + blockIdx.x] = a;
        g_pvs[tb * 9 + blockIdx.x] = v;
    }
}

// ---------------------------------------------------------------------------
// 3) finalize gs (deterministic partial sum) + write gs output
// ---------------------------------------------------------------------------
__global__ void finalize_kernel(float* __restrict__ d_out) {
    int tb = threadIdx.x;
    if (tb >= NTB) return;
    float gs = 0.f, vs = 0.f;
    for (int i = 0; i < 9; i++) { gs += g_pgs[tb * 9 + i]; vs += g_pvs[tb * 9 + i]; }
    float g = (vs < 1e-4f) ? 0.f : (gs / vs) * (1.f / 128.f);
    g_gs[tb] = g;
    // gs output: offset = B*257*HW + B*HW, shape (T,B) flattened as t*B+b
    d_out[(size_t)B_ * 257 * HW_ + (size_t)B_ * HW_ + tb] = g;
}

// ---------------------------------------------------------------------------
// 4) per-pixel softmax over T: c_match scratch + c_mask outputs
// ---------------------------------------------------------------------------
__global__ void __launch_bounds__(256) cmatch_kernel(float* __restrict__ d_out) {
    int idx = blockIdx.x * 256 + threadIdx.x;     // 0 .. B_*HW4_-1
    int b = idx / HW4_;
    int i4 = idx - b * HW4_;

    float gsv[T_];
    float rvv[T_][4];
#pragma unroll
    for (int t = 0; t < T_; t++) {
        gsv[t] = g_gs[t * B_ + b];
        float4 r = ((const float4*)g_rv)[(t * B_ + b) * HW4_ + i4];
        rvv[t][0] = r.x; rvv[t][1] = r.y; rvv[t][2] = r.z; rvv[t][3] = r.w;
    }

    float cm[T_][4];
    float msk[4];
#pragma unroll
    for (int j = 0; j < 4; j++) {
        float mx = -1e30f;
#pragma unroll
        for (int t = 0; t < T_; t++) mx = fmaxf(mx, gsv[t] * rvv[t][j]);
        float ms = 0.f;
#pragma unroll
        for (int t = 0; t < T_; t++) {
            float e = expf(gsv[t] * rvv[t][j] - mx) * rvv[t][j];
            cm[t][j] = e;
            ms += e;
        }
        float msd = ms + ((ms < 1e-4f) ? 1.f : 0.f);
        float inv = 1.f / msd;
#pragma unroll
        for (int t = 0; t < T_; t++) cm[t][j] *= inv;
        msk[j] = 1.f - ms * inv;
    }

#pragma unroll
    for (int t = 0; t < T_; t++)
        ((float4*)g_cm)[(t * B_ + b) * HW4_ + i4] =
            make_float4(cm[t][0], cm[t][1], cm[t][2], cm[t][3]);

    float4 cmask4 = make_float4(msk[0], msk[1], msk[2], msk[3]);
    float4* outp = (float4*)d_out;
    outp[((size_t)b * 257 + 256) * HW4_ + i4] = cmask4;              // out channel 256
    outp[(size_t)B_ * 257 * HW4_ + (size_t)b * HW4_ + i4] = cmask4;  // c_mask output
}

// ---------------------------------------------------------------------------
// 5) c_out[b,c,p] = sum_t r_feats * c_match.  grid = (9, 16 c-chunks, 4 b)
// ---------------------------------------------------------------------------
__global__ void __launch_bounds__(256) pass2_kernel(const float* __restrict__ values,
                                                    float* __restrict__ d_out) {
    int i4 = blockIdx.x * 256 + threadIdx.x;   // 0..2303
    int c0 = blockIdx.y * 8;
    int b = blockIdx.z;

    float4 cm[T_];
#pragma unroll
    for (int t = 0; t < T_; t++)
        cm[t] = ((const float4*)g_cm)[(t * B_ + b) * HW4_ + i4];

    const float4* rfb = (const float4*)values;
    float4* outp = (float4*)d_out;
    for (int cc = 0; cc < 8; cc++) {
        int c = c0 + cc;
        float4 acc = make_float4(0.f, 0.f, 0.f, 0.f);
#pragma unroll
        for (int t = 0; t < T_; t++) {
            float4 r = __ldg(rfb + ((size_t)(B_ + t * B_ + b) * C_ + c) * HW4_ + i4);
            acc.x += r.x * cm[t].x; acc.y += r.y * cm[t].y;
            acc.z += r.z * cm[t].z; acc.w += r.w * cm[t].w;
        }
        outp[((size_t)b * 257 + 128 + c) * HW4_ + i4] = acc;
    }
}

// ---------------------------------------------------------------------------
extern "C" void kernel_launch(void* const* d_in, const int* in_sizes, int n_in,
                              void* d_out, int out_size) {
    const float* values = (const float*)d_in[0];   // (9,4,128,96,96)
    const float* tvmap  = (const float*)d_in[1];   // (4,1,384,384)
    const float* rvmaps = (const float*)d_in[2];   // (8,4,1,384,384)
    float* out = (float*)d_out;

    resize_kernel<<<(NMAP * HW_ + 255) / 256, 256>>>(tvmap, rvmaps);

    dim3 g1(9, NTB);
    pass1_kernel<<<g1, 256>>>(values);

    finalize_kernel<<<1, 32>>>(out);

    cmatch_kernel<<<(B_ * HW4_) / 256, 256>>>(out);

    dim3 g2(9, 16, B_);
    pass2_kernel<<<g2, 256>>>(values, out);

    // out[:, 0:128] = t_feat  (contiguous per-b blocks)
    for (int b = 0; b < B_; b++) {
        cudaMemcpyAsync(out + (size_t)b * 257 * HW_,
                        values + (size_t)b * C_ * HW_,
                        (size_t)C_ * HW_ * sizeof(float),
                        cudaMemcpyDeviceToDevice);
    }
}

// round 2
// speedup vs baseline: 1.3084x; 1.3084x over previous
#include <cuda_runtime.h>

#define T_ 8
#define B_ 4
#define C_ 128
#define HW_ 9216      // 96*96
#define HW4_ 2304     // HW_/4
#define NMAP 36       // T*B + B maps to resize
#define NTB 32        // T*B

// scratch (static __device__ — no allocation)
__device__ float g_tv[B_ * HW_];
__device__ float g_rv[NTB * HW_];
__device__ float g_cm[NTB * HW_];
__device__ float g_pgs[NTB * 36];   // 9 pixel tiles x 4 c-chunks
__device__ float g_pvs[NTB * 9];

// ---------------------------------------------------------------------------
// 1) antialiased (jax-style) 384->96 resize + threshold > 0.5
// ---------------------------------------------------------------------------
__global__ void resize_kernel(const float* __restrict__ tvmap,
                              const float* __restrict__ rvmaps) {
    int idx = blockIdx.x * blockDim.x + threadIdx.x;
    if (idx >= NMAP * HW_) return;
    int m = idx / HW_;
    int p = idx - m * HW_;
    int oy = p / 96, ox = p - oy * 96;

    const float* src = (m < B_) ? (tvmap + (size_t)m * 147456)
                                : (rvmaps + (size_t)(m - B_) * 147456);

    const float wtab[8] = {1.f, 3.f, 5.f, 7.f, 7.f, 5.f, 3.f, 1.f};
    int iy0 = 4 * oy - 2, ix0 = 4 * ox - 2;

    float wx[8];
    float wxs = 0.f;
#pragma unroll
    for (int k = 0; k < 8; k++) {
        int ix = ix0 + k;
        wx[k] = (ix >= 0 && ix < 384) ? wtab[k] : 0.f;
        wxs += wx[k];
    }

    float acc = 0.f, wys = 0.f;
#pragma unroll
    for (int ky = 0; ky < 8; ky++) {
        int iy = iy0 + ky;
        if (iy < 0 || iy >= 384) continue;
        wys += wtab[ky];
        const float* row = src + iy * 384;
        float ra = 0.f;
#pragma unroll
        for (int kx = 0; kx < 8; kx++) {
            if (wx[kx] != 0.f) ra += wx[kx] * row[ix0 + kx];
        }
        acc += wtab[ky] * ra;
    }
    float val = acc / (wys * wxs);
    float bin = (val > 0.5f) ? 1.f : 0.f;
    if (m < B_) g_tv[m * HW_ + p] = bin;
    else        g_rv[(m - B_) * HW_ + p] = bin;
}

// ---------------------------------------------------------------------------
// 2) masked correlation partials + t_feat passthrough to output.
//    grid = (9 pixel tiles, 32 tb, 4 c-chunks of 32)
// ---------------------------------------------------------------------------
__global__ void __launch_bounds__(256) pass1_kernel(const float* __restrict__ values,
                                                    float* __restrict__ d_out) {
    int tb = blockIdx.y;
    int b = tb & 3;
    int chunk = blockIdx.z;
    int c0 = chunk * 32;
    int i4 = blockIdx.x * 256 + threadIdx.x;   // 0..2303

    const float4* tf = (const float4*)values + ((size_t)b * C_ + c0) * HW4_ + i4;
    const float4* rf = (const float4*)values + ((size_t)(B_ + tb) * C_ + c0) * HW4_ + i4;
    bool writeT = (tb < B_);   // t==0 blocks copy t_feat into out channels 0..127
    float4* outp = (float4*)d_out + ((size_t)b * 257 + c0) * HW4_ + i4;

    float4 acc = make_float4(0.f, 0.f, 0.f, 0.f);
#pragma unroll 8
    for (int c = 0; c < 32; c++) {
        float4 a = __ldg(tf + c * HW4_);
        float4 r = __ldcs(rf + c * HW4_);
        if (writeT) outp[c * HW4_] = a;
        acc.x += a.x * r.x; acc.y += a.y * r.y;
        acc.z += a.z * r.z; acc.w += a.w * r.w;
    }

    float4 tv = ((const float4*)g_tv)[b * HW4_ + i4];
    float4 rv = ((const float4*)g_rv)[tb * HW4_ + i4];
    float m0 = tv.x * rv.x, m1 = tv.y * rv.y, m2 = tv.z * rv.z, m3 = tv.w * rv.w;
    float lg = acc.x * m0 + acc.y * m1 + acc.z * m2 + acc.w * m3;
    float lv = m0 + m1 + m2 + m3;

#pragma unroll
    for (int o = 16; o > 0; o >>= 1) {
        lg += __shfl_down_sync(0xffffffffu, lg, o);
        lv += __shfl_down_sync(0xffffffffu, lv, o);
    }
    __shared__ float sg[8], sv[8];
    int lane = threadIdx.x & 31, w = threadIdx.x >> 5;
    if (lane == 0) { sg[w] = lg; sv[w] = lv; }
    __syncthreads();
    if (threadIdx.x == 0) {
        float a = 0.f, v = 0.f;
#pragma unroll
        for (int i = 0; i < 8; i++) { a += sg[i]; v += sv[i]; }
        g_pgs[tb * 36 + blockIdx.x * 4 + chunk] = a;
        if (chunk == 0) g_pvs[tb * 9 + blockIdx.x] = v;
    }
}

// ---------------------------------------------------------------------------
// 3) fused gs-finalize + per-pixel softmax over T (scalar, 288 x 128)
//    writes c_match scratch, c_mask (x2), gs output
// ---------------------------------------------------------------------------
__global__ void __launch_bounds__(128) cmatch_kernel(float* __restrict__ d_out) {
    const int BPB = HW_ / 128;           // 72 pixel-blocks per b
    int b = blockIdx.x / BPB;
    int pblk = blockIdx.x - b * BPB;
    int p = pblk * 128 + threadIdx.x;

    __shared__ float sgs[T_];
    if (threadIdx.x < T_) {
        int t = threadIdx.x;
        int tb = t * B_ + b;
        float gsum = 0.f, vsum = 0.f;
#pragma unroll
        for (int i = 0; i < 36; i++) gsum += g_pgs[tb * 36 + i];
#pragma unroll
        for (int i = 0; i < 9; i++) vsum += g_pvs[tb * 9 + i];
        float g = (vsum < 1e-4f) ? 0.f : (gsum / vsum) * (1.f / 128.f);
        sgs[t] = g;
        if (pblk == 0)
            d_out[(size_t)B_ * 257 * HW_ + (size_t)B_ * HW_ + tb] = g;
    }
    __syncthreads();

    float rvv[T_];
#pragma unroll
    for (int t = 0; t < T_; t++)
        rvv[t] = g_rv[(t * B_ + b) * HW_ + p];

    float mx = -1e30f;
#pragma unroll
    for (int t = 0; t < T_; t++) mx = fmaxf(mx, sgs[t] * rvv[t]);
    float cm[T_];
    float ms = 0.f;
#pragma unroll
    for (int t = 0; t < T_; t++) {
        float e = expf(sgs[t] * rvv[t] - mx) * rvv[t];
        cm[t] = e;
        ms += e;
    }
    float msd = ms + ((ms < 1e-4f) ? 1.f : 0.f);
    float inv = 1.f / msd;
#pragma unroll
    for (int t = 0; t < T_; t++)
        g_cm[(t * B_ + b) * HW_ + p] = cm[t] * inv;

    float cmask = 1.f - ms * inv;
    d_out[((size_t)b * 257 + 256) * HW_ + p] = cmask;                 // out ch 256
    d_out[(size_t)B_ * 257 * HW_ + (size_t)b * HW_ + p] = cmask;      // c_mask output
}

// ---------------------------------------------------------------------------
// 4) c_out[b,c,p] = sum_t r_feats * c_match.  grid = (9, 16 c-chunks, 4 b)
// ---------------------------------------------------------------------------
__global__ void __launch_bounds__(256) pass2_kernel(const float* __restrict__ values,
                                                    float* __restrict__ d_out) {
    int i4 = blockIdx.x * 256 + threadIdx.x;   // 0..2303
    int c0 = blockIdx.y * 8;
    int b = blockIdx.z;

    float4 cm[T_];
#pragma unroll
    for (int t = 0; t < T_; t++)
        cm[t] = ((const float4*)g_cm)[(t * B_ + b) * HW4_ + i4];

    const float4* rfb = (const float4*)values;
    float4* outp = (float4*)d_out;
#pragma unroll
    for (int cc = 0; cc < 8; cc++) {
        int c = c0 + cc;
        float4 acc = make_float4(0.f, 0.f, 0.f, 0.f);
#pragma unroll
        for (int t = 0; t < T_; t++) {
            float4 r = __ldcs(rfb + ((size_t)(B_ + t * B_ + b) * C_ + c) * HW4_ + i4);
            acc.x += r.x * cm[t].x; acc.y += r.y * cm[t].y;
            acc.z += r.z * cm[t].z; acc.w += r.w * cm[t].w;
        }
        outp[((size_t)b * 257 + 128 + c) * HW4_ + i4] = acc;
    }
}

// ---------------------------------------------------------------------------
extern "C" void kernel_launch(void* const* d_in, const int* in_sizes, int n_in,
                              void* d_out, int out_size) {
    const float* values = (const float*)d_in[0];   // (9,4,128,96,96)
    const float* tvmap  = (const float*)d_in[1];   // (4,1,384,384)
    const float* rvmaps = (const float*)d_in[2];   // (8,4,1,384,384)
    float* out = (float*)d_out;

    resize_kernel<<<(NMAP * HW_ + 255) / 256, 256>>>(tvmap, rvmaps);

    dim3 g1(9, NTB, 4);
    pass1_kernel<<<g1, 256>>>(values, out);

    cmatch_kernel<<<B_ * (HW_ / 128), 128>>>(out);

    dim3 g2(9, 16, B_);
    pass2_kernel<<<g2, 256>>>(values, out);
}